// round 8
// baseline (speedup 1.0000x reference)
#include <cuda_runtime.h>
#include <cuda_fp16.h>
#include <cstdint>
#include <cstddef>

#define P_C     16
#define W_C     8
#define F_IN_C  128
#define F_OUT_C 128
#define NPAD    100352   // padded dst count (multiple of 64, >= any n_dst tile span)

// h_neigh in fragment-plane layout: plane[kstep 0..15][dst][4 x half2 (k, k+4)]
__device__ uint4 g_hplane[(size_t)16 * NPAD];

// ---------------------------------------------------------------------------
// Kernel 1 (fused decode+gather+mean), fp16 codebook in smem (64 KB).
// Output: fp16 packed fragment planes (one STG.128 per partition per dst).
// ---------------------------------------------------------------------------
#define GW_THREADS 512
#define GW_BLOCKS  444

__global__ __launch_bounds__(GW_THREADS, 3) void gather_fused_kernel(
    const int* __restrict__ codes,
    const int* __restrict__ indices,
    const int* __restrict__ indptr,
    const float* __restrict__ codebook,
    int n_dst) {
    extern __shared__ __half2 cbh[];   // 16 KB half2 = 64 KB

    int tid  = threadIdx.x;
    int lane = tid & 31;
    int wid  = tid >> 5;

#pragma unroll
    for (int i = 0; i < 8; i++) {
        int blk = i * GW_THREADS + tid;          // 0..4095
        const float4* s = reinterpret_cast<const float4*>(codebook + blk * 8);
        float4 a = __ldg(s);
        float4 b = __ldg(s + 1);
        __half2 h0 = __floats2half2_rn(a.x, a.y);
        __half2 h1 = __floats2half2_rn(a.z, a.w);
        __half2 h2 = __floats2half2_rn(b.x, b.y);
        __half2 h3 = __floats2half2_rn(b.z, b.w);
        uint4 pk;
        pk.x = *reinterpret_cast<uint32_t*>(&h0);
        pk.y = *reinterpret_cast<uint32_t*>(&h1);
        pk.z = *reinterpret_cast<uint32_t*>(&h2);
        pk.w = *reinterpret_cast<uint32_t*>(&h3);
        reinterpret_cast<uint4*>(cbh)[blk] = pk;
    }
    __syncthreads();

    int p = lane & 15;
    int h = lane >> 4;
    const __half2* cb_p = cbh + (p << 10);

    int nwarps = GW_BLOCKS * (GW_THREADS / 32);
    for (int dst = blockIdx.x * (GW_THREADS / 32) + wid; dst < n_dst; dst += nwarps) {
        int start = __ldg(indptr + dst);
        int deg   = __ldg(indptr + dst + 1) - start;

        float4 lo, hi;   // lanes<16: features p*8..+3 (lo) and p*8+4..+7 (hi)

        if (deg == 16) {
            int my_idx = __ldg(indices + start + (lane & 15));
            int c[8];
#pragma unroll
            for (int s = 0; s < 8; s++) {
                int src = __shfl_sync(0xffffffffu, my_idx, 2 * s + h);
                c[s] = __ldg(codes + src * P_C + p);
            }
            __half2 acc0 = __float2half2_rn(0.f), acc1 = acc0, acc2 = acc0, acc3 = acc0;
#pragma unroll
            for (int s = 0; s < 8; s++) {
                uint4 v = *reinterpret_cast<const uint4*>(cb_p + c[s] * 4);
                acc0 = __hadd2(acc0, *reinterpret_cast<__half2*>(&v.x));
                acc1 = __hadd2(acc1, *reinterpret_cast<__half2*>(&v.y));
                acc2 = __hadd2(acc2, *reinterpret_cast<__half2*>(&v.z));
                acc3 = __hadd2(acc3, *reinterpret_cast<__half2*>(&v.w));
            }
            uint32_t u0 = *reinterpret_cast<uint32_t*>(&acc0);
            uint32_t u1 = *reinterpret_cast<uint32_t*>(&acc1);
            uint32_t u2 = *reinterpret_cast<uint32_t*>(&acc2);
            uint32_t u3 = *reinterpret_cast<uint32_t*>(&acc3);
            uint32_t q0 = __shfl_down_sync(0xffffffffu, u0, 16);
            uint32_t q1 = __shfl_down_sync(0xffffffffu, u1, 16);
            uint32_t q2 = __shfl_down_sync(0xffffffffu, u2, 16);
            uint32_t q3 = __shfl_down_sync(0xffffffffu, u3, 16);
            float2 f0 = __half22float2(*reinterpret_cast<__half2*>(&u0));
            float2 f1 = __half22float2(*reinterpret_cast<__half2*>(&u1));
            float2 f2 = __half22float2(*reinterpret_cast<__half2*>(&u2));
            float2 f3 = __half22float2(*reinterpret_cast<__half2*>(&u3));
            float2 g0 = __half22float2(*reinterpret_cast<__half2*>(&q0));
            float2 g1 = __half22float2(*reinterpret_cast<__half2*>(&q1));
            float2 g2 = __half22float2(*reinterpret_cast<__half2*>(&q2));
            float2 g3 = __half22float2(*reinterpret_cast<__half2*>(&q3));
            const float s16 = 1.0f / 16.0f;
            lo = make_float4((f0.x + g0.x) * s16, (f0.y + g0.y) * s16,
                             (f1.x + g1.x) * s16, (f1.y + g1.y) * s16);
            hi = make_float4((f2.x + g2.x) * s16, (f2.y + g2.y) * s16,
                             (f3.x + g3.x) * s16, (f3.y + g3.y) * s16);
        } else {
            // generic: lane (p,h) covers features p*8 + h*4 .. +4
            float4 acc = make_float4(0.f, 0.f, 0.f, 0.f);
            for (int e = 0; e < deg; e++) {
                int src = __ldg(indices + start + e);
                int c = __ldg(codes + src * P_C + p);
                __half2 a = cb_p[c * 4 + h * 2];
                __half2 b = cb_p[c * 4 + h * 2 + 1];
                float2 fa = __half22float2(a), fb = __half22float2(b);
                acc.x += fa.x; acc.y += fa.y; acc.z += fb.x; acc.w += fb.y;
            }
            float s = 1.0f / fmaxf((float)deg, 1.0f);
            acc.x *= s; acc.y *= s; acc.z *= s; acc.w *= s;
            // lanes<16 gather the h=1 half
            float4 acch;
            acch.x = __shfl_down_sync(0xffffffffu, acc.x, 16);
            acch.y = __shfl_down_sync(0xffffffffu, acc.y, 16);
            acch.z = __shfl_down_sync(0xffffffffu, acc.z, 16);
            acch.w = __shfl_down_sync(0xffffffffu, acc.w, 16);
            lo = acc; hi = acch;
        }

        if (lane < 16) {
            // pack pairs (v_j, v_{j+4}) and store one STG.128 to plane p
            __half2 q0 = __floats2half2_rn(lo.x, hi.x);
            __half2 q1 = __floats2half2_rn(lo.y, hi.y);
            __half2 q2 = __floats2half2_rn(lo.z, hi.z);
            __half2 q3 = __floats2half2_rn(lo.w, hi.w);
            uint4 pk;
            pk.x = *reinterpret_cast<uint32_t*>(&q0);
            pk.y = *reinterpret_cast<uint32_t*>(&q1);
            pk.z = *reinterpret_cast<uint32_t*>(&q2);
            pk.w = *reinterpret_cast<uint32_t*>(&q3);
            g_hplane[(size_t)p * NPAD + dst] = pk;
        }
    }
}

// ---------------------------------------------------------------------------
// Kernel 2: persistent tf32 mma.sync GEMM, 256 thr (8 warps, 2wm x 4wn),
// tile 64(M) x 128(N) x 256(K). 3 CTAs/SM. Only B in smem (packed fp16
// fragments, conflict-free lds32). A fragments load straight from global:
// neighbor = fp16 planes (2x LDG.32), self = natural fp32 (4x LDG.32 + cvt).
// No __syncthreads in the tile loop.
// ---------------------------------------------------------------------------
__device__ __forceinline__ uint32_t f2tf32(float x) {
    uint32_t r;
    asm("cvt.rna.tf32.f32 %0, %1;" : "=r"(r) : "f"(x));
    return r;
}
__device__ __forceinline__ void mma_tf32(float* d, const uint32_t* a, const uint32_t* b) {
    asm volatile(
        "mma.sync.aligned.m16n8k8.row.col.f32.tf32.tf32.f32 "
        "{%0,%1,%2,%3}, {%4,%5,%6,%7}, {%8,%9}, {%0,%1,%2,%3};"
        : "+f"(d[0]), "+f"(d[1]), "+f"(d[2]), "+f"(d[3])
        : "r"(a[0]), "r"(a[1]), "r"(a[2]), "r"(a[3]), "r"(b[0]), "r"(b[1]));
}

#define GT        256
#define GEMM_GRID 444
// B smem: [16 nblocks][32 ksteps][32 lanes + 2 pad] uint32 = 69632 B
#define BLANE 34
#define SMB_TOT (16 * 32 * BLANE * 4)

__global__ __launch_bounds__(GT, 3) void gemm_mma_kernel(
    const float* __restrict__ hself,
    const float* __restrict__ Wn,
    const float* __restrict__ Ws,
    const float* __restrict__ bias,
    float* __restrict__ out,
    int n_dst) {
    extern __shared__ uint32_t sB[];   // [nblock][kstep][lane]
    int tid  = threadIdx.x;
    int wid  = tid >> 5;
    int lane = tid & 31;
    int wm   = wid >> 2;   // 0..1 : rows wm*32..+31
    int wn   = wid & 3;    // 0..3 : cols wn*32..+31

    // ---- stage B once: packed half2 fragments ----
    // slot (nblock, kstep, l): n = nblock*8 + (l>>2), klo = kstep*8 + (l&3)
#pragma unroll
    for (int i = 0; i < 64; i++) {
        int slot   = i * GT + tid;            // 0..16383
        int nblock = slot >> 10;
        int kstep  = (slot >> 5) & 31;
        int l      = slot & 31;
        int n      = nblock * 8 + (l >> 2);
        int klo    = kstep * 8 + (l & 3);
        int khi    = klo + 4;
        float flo = (klo < 128) ? __ldg(Wn + n * 128 + klo) : __ldg(Ws + n * 128 + klo - 128);
        float fhi = (khi < 128) ? __ldg(Wn + n * 128 + khi) : __ldg(Ws + n * 128 + khi - 128);
        __half2 hp = __floats2half2_rn(flo, fhi);
        sB[(nblock * 32 + kstep) * BLANE + l] = *reinterpret_cast<uint32_t*>(&hp);
    }
    __syncthreads();

    int colq = (lane & 3) * 2;
    int rowq = lane >> 2;
    float bj[4][2];
#pragma unroll
    for (int j = 0; j < 4; j++) {
        float2 b2 = *reinterpret_cast<const float2*>(bias + wn * 32 + j * 8 + colq);
        bj[j][0] = b2.x; bj[j][1] = b2.y;
    }

    const uint32_t* plane = reinterpret_cast<const uint32_t*>(g_hplane);
    int ntiles = (n_dst + 63) >> 6;

    for (int tile = blockIdx.x; tile < ntiles; tile += gridDim.x) {
        int m0 = tile << 6;

        float acc[2][4][4];
#pragma unroll
        for (int mi = 0; mi < 2; mi++)
#pragma unroll
            for (int j = 0; j < 4; j++)
#pragma unroll
                for (int r = 0; r < 4; r++) acc[mi][j][r] = 0.f;

#pragma unroll
        for (int sg = 0; sg < 32; sg++) {
            // B fragments (conflict-free lds32 + unpack)
            uint32_t bf[4][2];
#pragma unroll
            for (int j = 0; j < 4; j++) {
                uint32_t u = sB[((wn * 4 + j) * 32 + sg) * BLANE + lane];
                float2 f = __half22float2(*reinterpret_cast<__half2*>(&u));
                bf[j][0] = __float_as_uint(f.x);
                bf[j][1] = __float_as_uint(f.y);
            }
#pragma unroll
            for (int mi = 0; mi < 2; mi++) {
                int mblock = wm * 2 + mi;
                int r = m0 + mblock * 16 + rowq;
                uint32_t a[4];
                if (sg < 16) {
                    // neighbor plane: word idx = (sg*NPAD + row)*4 + (lane&3)
                    size_t base = ((size_t)sg * NPAD + r) * 4 + (lane & 3);
                    uint32_t w0 = __ldg(plane + base);          // row r   : (klo, khi)
                    uint32_t w1 = __ldg(plane + base + 32);     // row r+8
                    float2 f0 = __half22float2(*reinterpret_cast<__half2*>(&w0));
                    float2 f1 = __half22float2(*reinterpret_cast<__half2*>(&w1));
                    a[0] = __float_as_uint(f0.x);   // (r,   klo)
                    a[1] = __float_as_uint(f1.x);   // (r+8, klo)
                    a[2] = __float_as_uint(f0.y);   // (r,   khi)
                    a[3] = __float_as_uint(f1.y);   // (r+8, khi)
                } else {
                    int k  = (sg - 16) * 8 + (lane & 3);
                    int r0 = (r     < n_dst) ? r     : n_dst - 1;
                    int r1 = (r + 8 < n_dst) ? r + 8 : n_dst - 1;
                    a[0] = f2tf32(__ldg(hself + (size_t)r0 * F_IN_C + k));
                    a[1] = f2tf32(__ldg(hself + (size_t)r1 * F_IN_C + k));
                    a[2] = f2tf32(__ldg(hself + (size_t)r0 * F_IN_C + k + 4));
                    a[3] = f2tf32(__ldg(hself + (size_t)r1 * F_IN_C + k + 4));
                }
#pragma unroll
                for (int j = 0; j < 4; j++)
                    mma_tf32(acc[mi][j], a, bf[j]);
            }
        }

        // ---- epilogue ----
#pragma unroll
        for (int mi = 0; mi < 2; mi++) {
            int r0 = m0 + (wm * 2 + mi) * 16 + rowq;
            int r1 = r0 + 8;
#pragma unroll
            for (int j = 0; j < 4; j++) {
                int col = wn * 32 + j * 8 + colq;
                if (r0 < n_dst) {
                    float2 o = make_float2(acc[mi][j][0] + bj[j][0],
                                           acc[mi][j][1] + bj[j][1]);
                    *reinterpret_cast<float2*>(out + (size_t)r0 * F_OUT_C + col) = o;
                }
                if (r1 < n_dst) {
                    float2 o = make_float2(acc[mi][j][2] + bj[j][0],
                                           acc[mi][j][3] + bj[j][1]);
                    *reinterpret_cast<float2*>(out + (size_t)r1 * F_OUT_C + col) = o;
                }
            }
        }
    }
}

// ---------------------------------------------------------------------------
// Launch
// ---------------------------------------------------------------------------
extern "C" void kernel_launch(void* const* d_in, const int* in_sizes, int n_in,
                              void* d_out, int out_size) {
    const int*   codes    = (const int*)d_in[0];
    const int*   indices  = (const int*)d_in[1];
    const int*   indptr   = (const int*)d_in[2];
    const float* h_self   = (const float*)d_in[3];
    const float* codebook = (const float*)d_in[4];
    const float* Wn       = (const float*)d_in[5];
    const float* Ws       = (const float*)d_in[6];
    const float* b_self   = (const float*)d_in[7];
    float* out = (float*)d_out;

    int n_dst = in_sizes[2] - 1;

    {
        const int cb_bytes = P_C * 256 * W_C * 2;   // 65536 (fp16)
        cudaFuncSetAttribute(gather_fused_kernel,
                             cudaFuncAttributeMaxDynamicSharedMemorySize, cb_bytes);
        gather_fused_kernel<<<GW_BLOCKS, GW_THREADS, cb_bytes>>>(
            codes, indices, indptr, codebook, n_dst);
    }
    {
        cudaFuncSetAttribute(gemm_mma_kernel,
                             cudaFuncAttributeMaxDynamicSharedMemorySize, SMB_TOT);
        gemm_mma_kernel<<<GEMM_GRID, GT, SMB_TOT>>>(
            h_self, Wn, Ws, b_self, out, n_dst);
    }
}

// round 9
// speedup vs baseline: 1.2057x; 1.2057x over previous
#include <cuda_runtime.h>
#include <cuda_fp16.h>
#include <cstdint>
#include <cstddef>

#define P_C     16
#define W_C     8
#define F_IN_C  128
#define F_OUT_C 128
#define NPAD    100352   // padded dst count (multiple of 64)

// Unified fp16 plane scratch: plane[kc][dst] = uint4 = 8 halfs, natural k order.
// kc 0..15  : neighbor features k = kc*8 .. +7
// kc 16..31 : self features     k = (kc-16)*8 .. +7
__device__ uint4 g_plane[(size_t)32 * NPAD];

// ---------------------------------------------------------------------------
// Kernel 1: fused decode+gather+mean (fp16 codebook in 64 KB smem) PLUS
// h_self -> fp16 plane conversion. After the cross-half shfl combine,
// lanes <16 store the neighbor plane, lanes >=16 convert+store the self plane.
// ---------------------------------------------------------------------------
#define GW_THREADS 512
#define GW_BLOCKS  444

__global__ __launch_bounds__(GW_THREADS, 3) void gather_fused_kernel(
    const int* __restrict__ codes,
    const int* __restrict__ indices,
    const int* __restrict__ indptr,
    const float* __restrict__ codebook,
    const float* __restrict__ hself,
    int n_dst) {
    extern __shared__ __half2 cbh[];   // 16 KB half2 = 64 KB

    int tid  = threadIdx.x;
    int lane = tid & 31;
    int wid  = tid >> 5;

#pragma unroll
    for (int i = 0; i < 8; i++) {
        int blk = i * GW_THREADS + tid;          // 0..4095
        const float4* s = reinterpret_cast<const float4*>(codebook + blk * 8);
        float4 a = __ldg(s);
        float4 b = __ldg(s + 1);
        __half2 h0 = __floats2half2_rn(a.x, a.y);
        __half2 h1 = __floats2half2_rn(a.z, a.w);
        __half2 h2 = __floats2half2_rn(b.x, b.y);
        __half2 h3 = __floats2half2_rn(b.z, b.w);
        uint4 pk;
        pk.x = *reinterpret_cast<uint32_t*>(&h0);
        pk.y = *reinterpret_cast<uint32_t*>(&h1);
        pk.z = *reinterpret_cast<uint32_t*>(&h2);
        pk.w = *reinterpret_cast<uint32_t*>(&h3);
        reinterpret_cast<uint4*>(cbh)[blk] = pk;
    }
    __syncthreads();

    int p = lane & 15;
    int h = lane >> 4;
    const __half2* cb_p = cbh + (p << 10);

    int nwarps = GW_BLOCKS * (GW_THREADS / 32);
    for (int dst = blockIdx.x * (GW_THREADS / 32) + wid; dst < n_dst; dst += nwarps) {
        int start = __ldg(indptr + dst);
        int deg   = __ldg(indptr + dst + 1) - start;

        float4 lo, hi;   // lanes<16: features p*8..+3 (lo), p*8+4..+7 (hi)

        if (deg == 16) {
            int my_idx = __ldg(indices + start + (lane & 15));
            int c[8];
#pragma unroll
            for (int s = 0; s < 8; s++) {
                int src = __shfl_sync(0xffffffffu, my_idx, 2 * s + h);
                c[s] = __ldg(codes + src * P_C + p);
            }
            __half2 acc0 = __float2half2_rn(0.f), acc1 = acc0, acc2 = acc0, acc3 = acc0;
#pragma unroll
            for (int s = 0; s < 8; s++) {
                uint4 v = *reinterpret_cast<const uint4*>(cb_p + c[s] * 4);
                acc0 = __hadd2(acc0, *reinterpret_cast<__half2*>(&v.x));
                acc1 = __hadd2(acc1, *reinterpret_cast<__half2*>(&v.y));
                acc2 = __hadd2(acc2, *reinterpret_cast<__half2*>(&v.z));
                acc3 = __hadd2(acc3, *reinterpret_cast<__half2*>(&v.w));
            }
            uint32_t u0 = *reinterpret_cast<uint32_t*>(&acc0);
            uint32_t u1 = *reinterpret_cast<uint32_t*>(&acc1);
            uint32_t u2 = *reinterpret_cast<uint32_t*>(&acc2);
            uint32_t u3 = *reinterpret_cast<uint32_t*>(&acc3);
            uint32_t q0 = __shfl_down_sync(0xffffffffu, u0, 16);
            uint32_t q1 = __shfl_down_sync(0xffffffffu, u1, 16);
            uint32_t q2 = __shfl_down_sync(0xffffffffu, u2, 16);
            uint32_t q3 = __shfl_down_sync(0xffffffffu, u3, 16);
            float2 f0 = __half22float2(*reinterpret_cast<__half2*>(&u0));
            float2 f1 = __half22float2(*reinterpret_cast<__half2*>(&u1));
            float2 f2 = __half22float2(*reinterpret_cast<__half2*>(&u2));
            float2 f3 = __half22float2(*reinterpret_cast<__half2*>(&u3));
            float2 g0 = __half22float2(*reinterpret_cast<__half2*>(&q0));
            float2 g1 = __half22float2(*reinterpret_cast<__half2*>(&q1));
            float2 g2 = __half22float2(*reinterpret_cast<__half2*>(&q2));
            float2 g3 = __half22float2(*reinterpret_cast<__half2*>(&q3));
            const float s16 = 1.0f / 16.0f;
            lo = make_float4((f0.x + g0.x) * s16, (f0.y + g0.y) * s16,
                             (f1.x + g1.x) * s16, (f1.y + g1.y) * s16);
            hi = make_float4((f2.x + g2.x) * s16, (f2.y + g2.y) * s16,
                             (f3.x + g3.x) * s16, (f3.y + g3.y) * s16);
        } else {
            float4 acc = make_float4(0.f, 0.f, 0.f, 0.f);
            for (int e = 0; e < deg; e++) {
                int src = __ldg(indices + start + e);
                int c = __ldg(codes + src * P_C + p);
                __half2 a = cb_p[c * 4 + h * 2];
                __half2 b = cb_p[c * 4 + h * 2 + 1];
                float2 fa = __half22float2(a), fb = __half22float2(b);
                acc.x += fa.x; acc.y += fa.y; acc.z += fb.x; acc.w += fb.y;
            }
            float s = 1.0f / fmaxf((float)deg, 1.0f);
            acc.x *= s; acc.y *= s; acc.z *= s; acc.w *= s;
            float4 acch;
            acch.x = __shfl_down_sync(0xffffffffu, acc.x, 16);
            acch.y = __shfl_down_sync(0xffffffffu, acc.y, 16);
            acch.z = __shfl_down_sync(0xffffffffu, acc.z, 16);
            acch.w = __shfl_down_sync(0xffffffffu, acc.w, 16);
            lo = acc; hi = acch;
        }

        if (lane < 16) {
            // neighbor plane p: halfs in natural k order
            __half2 q0 = __floats2half2_rn(lo.x, lo.y);
            __half2 q1 = __floats2half2_rn(lo.z, lo.w);
            __half2 q2 = __floats2half2_rn(hi.x, hi.y);
            __half2 q3 = __floats2half2_rn(hi.z, hi.w);
            uint4 pk;
            pk.x = *reinterpret_cast<uint32_t*>(&q0);
            pk.y = *reinterpret_cast<uint32_t*>(&q1);
            pk.z = *reinterpret_cast<uint32_t*>(&q2);
            pk.w = *reinterpret_cast<uint32_t*>(&q3);
            g_plane[(size_t)p * NPAD + dst] = pk;
        } else {
            // self plane p: convert h_self[dst][p*8..+7]
            const float4* hs = reinterpret_cast<const float4*>(
                hself + (size_t)dst * F_IN_C + p * 8);
            float4 a = __ldg(hs);
            float4 b = __ldg(hs + 1);
            __half2 q0 = __floats2half2_rn(a.x, a.y);
            __half2 q1 = __floats2half2_rn(a.z, a.w);
            __half2 q2 = __floats2half2_rn(b.x, b.y);
            __half2 q3 = __floats2half2_rn(b.z, b.w);
            uint4 pk;
            pk.x = *reinterpret_cast<uint32_t*>(&q0);
            pk.y = *reinterpret_cast<uint32_t*>(&q1);
            pk.z = *reinterpret_cast<uint32_t*>(&q2);
            pk.w = *reinterpret_cast<uint32_t*>(&q3);
            g_plane[(size_t)(16 + p) * NPAD + dst] = pk;
        }
    }
}

// ---------------------------------------------------------------------------
// Kernel 2: fp16 mma.sync (m16n8k16) GEMM, 256 thr (8 warps, 2wm x 4wn),
// tile 64(M) x 128(N) x 256(K). B in 64 KB smem as packed half2 fragments
// (conflict-free lds32). A fragments = coalesced LDG.32 from fp16 planes
// (word idx = base + lane, nL=1). No cvt, no syncthreads in tile loop.
// ---------------------------------------------------------------------------
__device__ __forceinline__ void mma_f16(float* d, const uint32_t* a, const uint32_t* b) {
    asm volatile(
        "mma.sync.aligned.m16n8k16.row.col.f32.f16.f16.f32 "
        "{%0,%1,%2,%3}, {%4,%5,%6,%7}, {%8,%9}, {%0,%1,%2,%3};"
        : "+f"(d[0]), "+f"(d[1]), "+f"(d[2]), "+f"(d[3])
        : "r"(a[0]), "r"(a[1]), "r"(a[2]), "r"(a[3]), "r"(b[0]), "r"(b[1]));
}

#define GT        256
#define GEMM_GRID 444
// sB[nblock 0..15][kb 0..15][half 0..1][lane 0..31] uint32 = 65536 B
#define SMB_TOT (16 * 16 * 2 * 32 * 4)

__global__ __launch_bounds__(GT, 3) void gemm_mma_kernel(
    const float* __restrict__ Wn,
    const float* __restrict__ Ws,
    const float* __restrict__ bias,
    float* __restrict__ out,
    int n_dst) {
    extern __shared__ uint32_t sB[];
    int tid  = threadIdx.x;
    int wid  = tid >> 5;
    int lane = tid & 31;
    int wm   = wid >> 2;   // 0..1 : rows wm*32..+31
    int wn   = wid & 3;    // 0..3 : cols wn*32..+31

    // ---- stage B once: packed half2 fp16 fragments ----
    // slot: lane=slot&31, half=(slot>>5)&1, kb=(slot>>6)&15, nblock=slot>>10
#pragma unroll
    for (int i = 0; i < 64; i++) {
        int slot   = i * GT + tid;
        int l      = slot & 31;
        int half_  = (slot >> 5) & 1;
        int kb     = (slot >> 6) & 15;
        int nblock = slot >> 10;
        int n  = nblock * 8 + (l >> 2);
        int k0 = kb * 16 + half_ * 8 + (l & 3) * 2;
        float flo = (k0     < 128) ? __ldg(Wn + n * 128 + k0)     : __ldg(Ws + n * 128 + k0 - 128);
        float fhi = (k0 + 1 < 128) ? __ldg(Wn + n * 128 + k0 + 1) : __ldg(Ws + n * 128 + k0 - 127);
        __half2 hp = __floats2half2_rn(flo, fhi);
        sB[slot] = *reinterpret_cast<uint32_t*>(&hp);
    }
    __syncthreads();

    int colq = (lane & 3) * 2;
    int rowq = lane >> 2;
    float bj[4][2];
#pragma unroll
    for (int j = 0; j < 4; j++) {
        float2 b2 = *reinterpret_cast<const float2*>(bias + wn * 32 + j * 8 + colq);
        bj[j][0] = b2.x; bj[j][1] = b2.y;
    }

    const uint32_t* plane = reinterpret_cast<const uint32_t*>(g_plane);
    int ntiles = (n_dst + 63) >> 6;

    for (int tile = blockIdx.x; tile < ntiles; tile += gridDim.x) {
        int m0 = tile << 6;

        float acc[2][4][4];
#pragma unroll
        for (int mi = 0; mi < 2; mi++)
#pragma unroll
            for (int j = 0; j < 4; j++)
#pragma unroll
                for (int r = 0; r < 4; r++) acc[mi][j][r] = 0.f;

#pragma unroll
        for (int kb = 0; kb < 16; kb++) {
            uint32_t bf[4][2];
#pragma unroll
            for (int j = 0; j < 4; j++) {
                int nblock = wn * 4 + j;
                bf[j][0] = sB[(((nblock * 16 + kb) * 2) + 0) * 32 + lane];
                bf[j][1] = sB[(((nblock * 16 + kb) * 2) + 1) * 32 + lane];
            }
#pragma unroll
            for (int mi = 0; mi < 2; mi++) {
                int r0 = m0 + (wm * 2 + mi) * 16;
                size_t base0 = ((size_t)(2 * kb)     * NPAD + r0) * 4;
                size_t base1 = ((size_t)(2 * kb + 1) * NPAD + r0) * 4;
                uint32_t a[4];
                a[0] = __ldg(plane + base0 + lane);        // (g,   k=2tg)
                a[1] = __ldg(plane + base0 + 32 + lane);   // (g+8, k=2tg)
                a[2] = __ldg(plane + base1 + lane);        // (g,   k+8)
                a[3] = __ldg(plane + base1 + 32 + lane);   // (g+8, k+8)
#pragma unroll
                for (int j = 0; j < 4; j++)
                    mma_f16(acc[mi][j], a, bf[j]);
            }
        }

        // ---- epilogue ----
#pragma unroll
        for (int mi = 0; mi < 2; mi++) {
            int r0 = m0 + (wm * 2 + mi) * 16 + rowq;
            int r1 = r0 + 8;
#pragma unroll
            for (int j = 0; j < 4; j++) {
                int col = wn * 32 + j * 8 + colq;
                if (r0 < n_dst) {
                    float2 o = make_float2(acc[mi][j][0] + bj[j][0],
                                           acc[mi][j][1] + bj[j][1]);
                    *reinterpret_cast<float2*>(out + (size_t)r0 * F_OUT_C + col) = o;
                }
                if (r1 < n_dst) {
                    float2 o = make_float2(acc[mi][j][2] + bj[j][0],
                                           acc[mi][j][3] + bj[j][1]);
                    *reinterpret_cast<float2*>(out + (size_t)r1 * F_OUT_C + col) = o;
                }
            }
        }
    }
}

// ---------------------------------------------------------------------------
// Launch
// ---------------------------------------------------------------------------
extern "C" void kernel_launch(void* const* d_in, const int* in_sizes, int n_in,
                              void* d_out, int out_size) {
    const int*   codes    = (const int*)d_in[0];
    const int*   indices  = (const int*)d_in[1];
    const int*   indptr   = (const int*)d_in[2];
    const float* h_self   = (const float*)d_in[3];
    const float* codebook = (const float*)d_in[4];
    const float* Wn       = (const float*)d_in[5];
    const float* Ws       = (const float*)d_in[6];
    const float* b_self   = (const float*)d_in[7];
    float* out = (float*)d_out;

    int n_dst = in_sizes[2] - 1;

    {
        const int cb_bytes = P_C * 256 * W_C * 2;   // 65536 (fp16)
        cudaFuncSetAttribute(gather_fused_kernel,
                             cudaFuncAttributeMaxDynamicSharedMemorySize, cb_bytes);
        gather_fused_kernel<<<GW_BLOCKS, GW_THREADS, cb_bytes>>>(
            codes, indices, indptr, codebook, h_self, n_dst);
    }
    {
        cudaFuncSetAttribute(gemm_mma_kernel,
                             cudaFuncAttributeMaxDynamicSharedMemorySize, SMB_TOT);
        gemm_mma_kernel<<<GEMM_GRID, GT, SMB_TOT>>>(
            Wn, Ws, b_self, out, n_dst);
    }
}

// round 10
// speedup vs baseline: 1.3059x; 1.0831x over previous
#include <cuda_runtime.h>
#include <cuda_fp16.h>
#include <cstdint>
#include <cstddef>

#define P_C     16
#define W_C     8
#define F_IN_C  128
#define F_OUT_C 128
#define NPAD    100352   // padded dst count (multiple of 128)

// Unified fp16 plane scratch: plane[kc][dst] = uint4 = 8 halfs, natural k order.
// kc 0..15  : neighbor features k = kc*8 .. +7
// kc 16..31 : self features     k = (kc-16)*8 .. +7
__device__ uint4 g_plane[(size_t)32 * NPAD];

// ---------------------------------------------------------------------------
// Kernel 1: fused decode+gather+mean (fp16 codebook in 64 KB smem) PLUS
// h_self -> fp16 plane conversion. 1024 thr, 2 CTAs/SM (100% occupancy).
// ---------------------------------------------------------------------------
#define GW_THREADS 1024
#define GW_BLOCKS  296

__global__ __launch_bounds__(GW_THREADS, 2) void gather_fused_kernel(
    const int* __restrict__ codes,
    const int* __restrict__ indices,
    const int* __restrict__ indptr,
    const float* __restrict__ codebook,
    const float* __restrict__ hself,
    int n_dst) {
    extern __shared__ __half2 cbh[];   // 16 KB half2 = 64 KB

    int tid  = threadIdx.x;
    int lane = tid & 31;
    int wid  = tid >> 5;

#pragma unroll
    for (int i = 0; i < 4; i++) {
        int blk = i * GW_THREADS + tid;          // 0..4095
        const float4* s = reinterpret_cast<const float4*>(codebook + blk * 8);
        float4 a = __ldg(s);
        float4 b = __ldg(s + 1);
        __half2 h0 = __floats2half2_rn(a.x, a.y);
        __half2 h1 = __floats2half2_rn(a.z, a.w);
        __half2 h2 = __floats2half2_rn(b.x, b.y);
        __half2 h3 = __floats2half2_rn(b.z, b.w);
        uint4 pk;
        pk.x = *reinterpret_cast<uint32_t*>(&h0);
        pk.y = *reinterpret_cast<uint32_t*>(&h1);
        pk.z = *reinterpret_cast<uint32_t*>(&h2);
        pk.w = *reinterpret_cast<uint32_t*>(&h3);
        reinterpret_cast<uint4*>(cbh)[blk] = pk;
    }
    __syncthreads();

    int p = lane & 15;
    int h = lane >> 4;
    const __half2* cb_p = cbh + (p << 10);

    int nwarps = GW_BLOCKS * (GW_THREADS / 32);
    for (int dst = blockIdx.x * (GW_THREADS / 32) + wid; dst < n_dst; dst += nwarps) {
        int start = __ldg(indptr + dst);
        int deg   = __ldg(indptr + dst + 1) - start;

        float4 lo, hi;   // lanes<16: features p*8..+3 (lo), p*8+4..+7 (hi)

        if (deg == 16) {
            int my_idx = __ldg(indices + start + (lane & 15));
            int c[8];
#pragma unroll
            for (int s = 0; s < 8; s++) {
                int src = __shfl_sync(0xffffffffu, my_idx, 2 * s + h);
                c[s] = __ldg(codes + src * P_C + p);
            }
            __half2 acc0 = __float2half2_rn(0.f), acc1 = acc0, acc2 = acc0, acc3 = acc0;
#pragma unroll
            for (int s = 0; s < 8; s++) {
                uint4 v = *reinterpret_cast<const uint4*>(cb_p + c[s] * 4);
                acc0 = __hadd2(acc0, *reinterpret_cast<__half2*>(&v.x));
                acc1 = __hadd2(acc1, *reinterpret_cast<__half2*>(&v.y));
                acc2 = __hadd2(acc2, *reinterpret_cast<__half2*>(&v.z));
                acc3 = __hadd2(acc3, *reinterpret_cast<__half2*>(&v.w));
            }
            uint32_t u0 = *reinterpret_cast<uint32_t*>(&acc0);
            uint32_t u1 = *reinterpret_cast<uint32_t*>(&acc1);
            uint32_t u2 = *reinterpret_cast<uint32_t*>(&acc2);
            uint32_t u3 = *reinterpret_cast<uint32_t*>(&acc3);
            uint32_t q0 = __shfl_down_sync(0xffffffffu, u0, 16);
            uint32_t q1 = __shfl_down_sync(0xffffffffu, u1, 16);
            uint32_t q2 = __shfl_down_sync(0xffffffffu, u2, 16);
            uint32_t q3 = __shfl_down_sync(0xffffffffu, u3, 16);
            float2 f0 = __half22float2(*reinterpret_cast<__half2*>(&u0));
            float2 f1 = __half22float2(*reinterpret_cast<__half2*>(&u1));
            float2 f2 = __half22float2(*reinterpret_cast<__half2*>(&u2));
            float2 f3 = __half22float2(*reinterpret_cast<__half2*>(&u3));
            float2 g0 = __half22float2(*reinterpret_cast<__half2*>(&q0));
            float2 g1 = __half22float2(*reinterpret_cast<__half2*>(&q1));
            float2 g2 = __half22float2(*reinterpret_cast<__half2*>(&q2));
            float2 g3 = __half22float2(*reinterpret_cast<__half2*>(&q3));
            const float s16 = 1.0f / 16.0f;
            lo = make_float4((f0.x + g0.x) * s16, (f0.y + g0.y) * s16,
                             (f1.x + g1.x) * s16, (f1.y + g1.y) * s16);
            hi = make_float4((f2.x + g2.x) * s16, (f2.y + g2.y) * s16,
                             (f3.x + g3.x) * s16, (f3.y + g3.y) * s16);
        } else {
            float4 acc = make_float4(0.f, 0.f, 0.f, 0.f);
            for (int e = 0; e < deg; e++) {
                int src = __ldg(indices + start + e);
                int c = __ldg(codes + src * P_C + p);
                __half2 a = cb_p[c * 4 + h * 2];
                __half2 b = cb_p[c * 4 + h * 2 + 1];
                float2 fa = __half22float2(a), fb = __half22float2(b);
                acc.x += fa.x; acc.y += fa.y; acc.z += fb.x; acc.w += fb.y;
            }
            float s = 1.0f / fmaxf((float)deg, 1.0f);
            acc.x *= s; acc.y *= s; acc.z *= s; acc.w *= s;
            float4 acch;
            acch.x = __shfl_down_sync(0xffffffffu, acc.x, 16);
            acch.y = __shfl_down_sync(0xffffffffu, acc.y, 16);
            acch.z = __shfl_down_sync(0xffffffffu, acc.z, 16);
            acch.w = __shfl_down_sync(0xffffffffu, acc.w, 16);
            lo = acc; hi = acch;
        }

        if (lane < 16) {
            __half2 q0 = __floats2half2_rn(lo.x, lo.y);
            __half2 q1 = __floats2half2_rn(lo.z, lo.w);
            __half2 q2 = __floats2half2_rn(hi.x, hi.y);
            __half2 q3 = __floats2half2_rn(hi.z, hi.w);
            uint4 pk;
            pk.x = *reinterpret_cast<uint32_t*>(&q0);
            pk.y = *reinterpret_cast<uint32_t*>(&q1);
            pk.z = *reinterpret_cast<uint32_t*>(&q2);
            pk.w = *reinterpret_cast<uint32_t*>(&q3);
            g_plane[(size_t)p * NPAD + dst] = pk;
        } else {
            const float4* hs = reinterpret_cast<const float4*>(
                hself + (size_t)dst * F_IN_C + p * 8);
            float4 a = __ldg(hs);
            float4 b = __ldg(hs + 1);
            __half2 q0 = __floats2half2_rn(a.x, a.y);
            __half2 q1 = __floats2half2_rn(a.z, a.w);
            __half2 q2 = __floats2half2_rn(b.x, b.y);
            __half2 q3 = __floats2half2_rn(b.z, b.w);
            uint4 pk;
            pk.x = *reinterpret_cast<uint32_t*>(&q0);
            pk.y = *reinterpret_cast<uint32_t*>(&q1);
            pk.z = *reinterpret_cast<uint32_t*>(&q2);
            pk.w = *reinterpret_cast<uint32_t*>(&q3);
            g_plane[(size_t)(16 + p) * NPAD + dst] = pk;
        }
    }
}

// ---------------------------------------------------------------------------
// Kernel 2: fp16 mma.sync (m16n8k16) GEMM. 8 warps ALL along M:
// CTA tile 128(M) x 128(N), warp tile 16(M) x 128(N). Each A fragment is
// loaded exactly once per CTA (coalesced LDG.32 from planes); B swept from
// 64 KB smem (conflict-free lds32). No redundancy, no tile-loop syncs.
// ---------------------------------------------------------------------------
__device__ __forceinline__ void mma_f16(float* d, const uint32_t* a, const uint32_t* b) {
    asm volatile(
        "mma.sync.aligned.m16n8k16.row.col.f32.f16.f16.f32 "
        "{%0,%1,%2,%3}, {%4,%5,%6,%7}, {%8,%9}, {%0,%1,%2,%3};"
        : "+f"(d[0]), "+f"(d[1]), "+f"(d[2]), "+f"(d[3])
        : "r"(a[0]), "r"(a[1]), "r"(a[2]), "r"(a[3]), "r"(b[0]), "r"(b[1]));
}

#define GT        256
#define GEMM_GRID 296
// sB[nblock 0..15][kb 0..15][half 0..1][lane 0..31] uint32 = 65536 B
#define SMB_TOT (16 * 16 * 2 * 32 * 4)

__global__ __launch_bounds__(GT, 2) void gemm_mma_kernel(
    const float* __restrict__ Wn,
    const float* __restrict__ Ws,
    const float* __restrict__ bias,
    float* __restrict__ out,
    int n_dst) {
    extern __shared__ uint32_t sB[];
    int tid  = threadIdx.x;
    int wid  = tid >> 5;
    int lane = tid & 31;

    // ---- stage B once: packed half2 fp16 fragments ----
#pragma unroll
    for (int i = 0; i < 64; i++) {
        int slot   = i * GT + tid;
        int l      = slot & 31;
        int half_  = (slot >> 5) & 1;
        int kb     = (slot >> 6) & 15;
        int nblock = slot >> 10;
        int n  = nblock * 8 + (l >> 2);
        int k0 = kb * 16 + half_ * 8 + (l & 3) * 2;
        float flo = (k0     < 128) ? __ldg(Wn + n * 128 + k0)     : __ldg(Ws + n * 128 + k0 - 128);
        float fhi = (k0 + 1 < 128) ? __ldg(Wn + n * 128 + k0 + 1) : __ldg(Ws + n * 128 + k0 - 127);
        __half2 hp = __floats2half2_rn(flo, fhi);
        sB[slot] = *reinterpret_cast<uint32_t*>(&hp);
    }
    __syncthreads();

    int colq = (lane & 3) * 2;
    int rowq = lane >> 2;

    const uint32_t* plane = reinterpret_cast<const uint32_t*>(g_plane);
    int ntiles = (n_dst + 127) >> 7;

    for (int tile = blockIdx.x; tile < ntiles; tile += gridDim.x) {
        int m0  = tile << 7;
        int r0w = m0 + wid * 16;      // this warp's 16 rows

        float acc[16][4];
#pragma unroll
        for (int j = 0; j < 16; j++)
#pragma unroll
            for (int r = 0; r < 4; r++) acc[j][r] = 0.f;

#pragma unroll 2
        for (int kb = 0; kb < 16; kb++) {
            size_t b0 = ((size_t)(2 * kb) * NPAD + r0w) * 4;
            size_t b1 = b0 + (size_t)NPAD * 4;
            uint32_t a[4];
            a[0] = __ldg(plane + b0 + lane);        // (r,   klo pair)
            a[1] = __ldg(plane + b0 + 32 + lane);   // (r+8, klo pair)
            a[2] = __ldg(plane + b1 + lane);        // (r,   khi pair)
            a[3] = __ldg(plane + b1 + 32 + lane);   // (r+8, khi pair)
#pragma unroll
            for (int nf = 0; nf < 16; nf++) {
                uint32_t bf[2];
                bf[0] = sB[(((nf * 16 + kb) * 2) + 0) * 32 + lane];
                bf[1] = sB[(((nf * 16 + kb) * 2) + 1) * 32 + lane];
                mma_f16(acc[nf], a, bf);
            }
        }

        // ---- epilogue: bias + store ----
        int r0 = r0w + rowq;
        int r1 = r0 + 8;
#pragma unroll
        for (int nf = 0; nf < 16; nf++) {
            int col = nf * 8 + colq;
            float2 b2 = *reinterpret_cast<const float2*>(bias + col);
            if (r0 < n_dst) {
                float2 o = make_float2(acc[nf][0] + b2.x, acc[nf][1] + b2.y);
                *reinterpret_cast<float2*>(out + (size_t)r0 * F_OUT_C + col) = o;
            }
            if (r1 < n_dst) {
                float2 o = make_float2(acc[nf][2] + b2.x, acc[nf][3] + b2.y);
                *reinterpret_cast<float2*>(out + (size_t)r1 * F_OUT_C + col) = o;
            }
        }
    }
}

// ---------------------------------------------------------------------------
// Launch
// ---------------------------------------------------------------------------
extern "C" void kernel_launch(void* const* d_in, const int* in_sizes, int n_in,
                              void* d_out, int out_size) {
    const int*   codes    = (const int*)d_in[0];
    const int*   indices  = (const int*)d_in[1];
    const int*   indptr   = (const int*)d_in[2];
    const float* h_self   = (const float*)d_in[3];
    const float* codebook = (const float*)d_in[4];
    const float* Wn       = (const float*)d_in[5];
    const float* Ws       = (const float*)d_in[6];
    const float* b_self   = (const float*)d_in[7];
    float* out = (float*)d_out;

    int n_dst = in_sizes[2] - 1;

    {
        const int cb_bytes = P_C * 256 * W_C * 2;   // 65536 (fp16)
        cudaFuncSetAttribute(gather_fused_kernel,
                             cudaFuncAttributeMaxDynamicSharedMemorySize, cb_bytes);
        gather_fused_kernel<<<GW_BLOCKS, GW_THREADS, cb_bytes>>>(
            codes, indices, indptr, codebook, h_self, n_dst);
    }
    {
        cudaFuncSetAttribute(gemm_mma_kernel,
                             cudaFuncAttributeMaxDynamicSharedMemorySize, SMB_TOT);
        gemm_mma_kernel<<<GEMM_GRID, GT, SMB_TOT>>>(
            Wn, Ws, b_self, out, n_dst);
    }
}

// round 11
// speedup vs baseline: 1.3306x; 1.0189x over previous
#include <cuda_runtime.h>
#include <cuda_fp16.h>
#include <cstdint>
#include <cstddef>

#define P_C     16
#define W_C     8
#define F_IN_C  128
#define F_OUT_C 128
#define NPAD    100352   // padded dst count

// Unified fp16 plane scratch: plane[kc][dst] = uint4 = 8 halfs, natural k order.
// kc 0..15 : neighbor features k = kc*8..+7 ; kc 16..31 : self features
__device__ uint4 g_plane[(size_t)32 * NPAD];

// ---------------------------------------------------------------------------
// Kernel 1: fused decode+gather+mean (fp16 codebook in 64 KB smem) PLUS
// h_self -> fp16 plane conversion. (unchanged from R10)
// ---------------------------------------------------------------------------
#define GW_THREADS 1024
#define GW_BLOCKS  296

__global__ __launch_bounds__(GW_THREADS, 2) void gather_fused_kernel(
    const int* __restrict__ codes,
    const int* __restrict__ indices,
    const int* __restrict__ indptr,
    const float* __restrict__ codebook,
    const float* __restrict__ hself,
    int n_dst) {
    extern __shared__ __half2 cbh[];   // 64 KB

    int tid  = threadIdx.x;
    int lane = tid & 31;
    int wid  = tid >> 5;

#pragma unroll
    for (int i = 0; i < 4; i++) {
        int blk = i * GW_THREADS + tid;
        const float4* s = reinterpret_cast<const float4*>(codebook + blk * 8);
        float4 a = __ldg(s);
        float4 b = __ldg(s + 1);
        __half2 h0 = __floats2half2_rn(a.x, a.y);
        __half2 h1 = __floats2half2_rn(a.z, a.w);
        __half2 h2 = __floats2half2_rn(b.x, b.y);
        __half2 h3 = __floats2half2_rn(b.z, b.w);
        uint4 pk;
        pk.x = *reinterpret_cast<uint32_t*>(&h0);
        pk.y = *reinterpret_cast<uint32_t*>(&h1);
        pk.z = *reinterpret_cast<uint32_t*>(&h2);
        pk.w = *reinterpret_cast<uint32_t*>(&h3);
        reinterpret_cast<uint4*>(cbh)[blk] = pk;
    }
    __syncthreads();

    int p = lane & 15;
    int h = lane >> 4;
    const __half2* cb_p = cbh + (p << 10);

    int nwarps = GW_BLOCKS * (GW_THREADS / 32);
    for (int dst = blockIdx.x * (GW_THREADS / 32) + wid; dst < n_dst; dst += nwarps) {
        int start = __ldg(indptr + dst);
        int deg   = __ldg(indptr + dst + 1) - start;

        float4 lo, hi;

        if (deg == 16) {
            int my_idx = __ldg(indices + start + (lane & 15));
            int c[8];
#pragma unroll
            for (int s = 0; s < 8; s++) {
                int src = __shfl_sync(0xffffffffu, my_idx, 2 * s + h);
                c[s] = __ldg(codes + src * P_C + p);
            }
            __half2 acc0 = __float2half2_rn(0.f), acc1 = acc0, acc2 = acc0, acc3 = acc0;
#pragma unroll
            for (int s = 0; s < 8; s++) {
                uint4 v = *reinterpret_cast<const uint4*>(cb_p + c[s] * 4);
                acc0 = __hadd2(acc0, *reinterpret_cast<__half2*>(&v.x));
                acc1 = __hadd2(acc1, *reinterpret_cast<__half2*>(&v.y));
                acc2 = __hadd2(acc2, *reinterpret_cast<__half2*>(&v.z));
                acc3 = __hadd2(acc3, *reinterpret_cast<__half2*>(&v.w));
            }
            uint32_t u0 = *reinterpret_cast<uint32_t*>(&acc0);
            uint32_t u1 = *reinterpret_cast<uint32_t*>(&acc1);
            uint32_t u2 = *reinterpret_cast<uint32_t*>(&acc2);
            uint32_t u3 = *reinterpret_cast<uint32_t*>(&acc3);
            uint32_t q0 = __shfl_down_sync(0xffffffffu, u0, 16);
            uint32_t q1 = __shfl_down_sync(0xffffffffu, u1, 16);
            uint32_t q2 = __shfl_down_sync(0xffffffffu, u2, 16);
            uint32_t q3 = __shfl_down_sync(0xffffffffu, u3, 16);
            float2 f0 = __half22float2(*reinterpret_cast<__half2*>(&u0));
            float2 f1 = __half22float2(*reinterpret_cast<__half2*>(&u1));
            float2 f2 = __half22float2(*reinterpret_cast<__half2*>(&u2));
            float2 f3 = __half22float2(*reinterpret_cast<__half2*>(&u3));
            float2 g0 = __half22float2(*reinterpret_cast<__half2*>(&q0));
            float2 g1 = __half22float2(*reinterpret_cast<__half2*>(&q1));
            float2 g2 = __half22float2(*reinterpret_cast<__half2*>(&q2));
            float2 g3 = __half22float2(*reinterpret_cast<__half2*>(&q3));
            const float s16 = 1.0f / 16.0f;
            lo = make_float4((f0.x + g0.x) * s16, (f0.y + g0.y) * s16,
                             (f1.x + g1.x) * s16, (f1.y + g1.y) * s16);
            hi = make_float4((f2.x + g2.x) * s16, (f2.y + g2.y) * s16,
                             (f3.x + g3.x) * s16, (f3.y + g3.y) * s16);
        } else {
            float4 acc = make_float4(0.f, 0.f, 0.f, 0.f);
            for (int e = 0; e < deg; e++) {
                int src = __ldg(indices + start + e);
                int c = __ldg(codes + src * P_C + p);
                __half2 a = cb_p[c * 4 + h * 2];
                __half2 b = cb_p[c * 4 + h * 2 + 1];
                float2 fa = __half22float2(a), fb = __half22float2(b);
                acc.x += fa.x; acc.y += fa.y; acc.z += fb.x; acc.w += fb.y;
            }
            float s = 1.0f / fmaxf((float)deg, 1.0f);
            acc.x *= s; acc.y *= s; acc.z *= s; acc.w *= s;
            float4 acch;
            acch.x = __shfl_down_sync(0xffffffffu, acc.x, 16);
            acch.y = __shfl_down_sync(0xffffffffu, acc.y, 16);
            acch.z = __shfl_down_sync(0xffffffffu, acc.z, 16);
            acch.w = __shfl_down_sync(0xffffffffu, acc.w, 16);
            lo = acc; hi = acch;
        }

        if (lane < 16) {
            __half2 q0 = __floats2half2_rn(lo.x, lo.y);
            __half2 q1 = __floats2half2_rn(lo.z, lo.w);
            __half2 q2 = __floats2half2_rn(hi.x, hi.y);
            __half2 q3 = __floats2half2_rn(hi.z, hi.w);
            uint4 pk;
            pk.x = *reinterpret_cast<uint32_t*>(&q0);
            pk.y = *reinterpret_cast<uint32_t*>(&q1);
            pk.z = *reinterpret_cast<uint32_t*>(&q2);
            pk.w = *reinterpret_cast<uint32_t*>(&q3);
            g_plane[(size_t)p * NPAD + dst] = pk;
        } else {
            const float4* hs = reinterpret_cast<const float4*>(
                hself + (size_t)dst * F_IN_C + p * 8);
            float4 a = __ldg(hs);
            float4 b = __ldg(hs + 1);
            __half2 q0 = __floats2half2_rn(a.x, a.y);
            __half2 q1 = __floats2half2_rn(a.z, a.w);
            __half2 q2 = __floats2half2_rn(b.x, b.y);
            __half2 q3 = __floats2half2_rn(b.z, b.w);
            uint4 pk;
            pk.x = *reinterpret_cast<uint32_t*>(&q0);
            pk.y = *reinterpret_cast<uint32_t*>(&q1);
            pk.z = *reinterpret_cast<uint32_t*>(&q2);
            pk.w = *reinterpret_cast<uint32_t*>(&q3);
            g_plane[(size_t)(16 + p) * NPAD + dst] = pk;
        }
    }
}

// ---------------------------------------------------------------------------
// Kernel 2: fp16 mma.sync (m16n8k16) GEMM. Warp tile 32(M) x 128(N)
// (2 m-frags), CTA tile 256(M) x 128(N), 8 warps all along M. Each bf
// register feeds 2 MMAs; B LDS bytes per output row halved vs R10.
// ---------------------------------------------------------------------------
__device__ __forceinline__ void mma_f16(float* d, const uint32_t* a, const uint32_t* b) {
    asm volatile(
        "mma.sync.aligned.m16n8k16.row.col.f32.f16.f16.f32 "
        "{%0,%1,%2,%3}, {%4,%5,%6,%7}, {%8,%9}, {%0,%1,%2,%3};"
        : "+f"(d[0]), "+f"(d[1]), "+f"(d[2]), "+f"(d[3])
        : "r"(a[0]), "r"(a[1]), "r"(a[2]), "r"(a[3]), "r"(b[0]), "r"(b[1]));
}

#define GT        256
#define GEMM_GRID 148
// sB[nblock 0..15][kb 0..15][half 0..1][lane 0..31] uint32 = 65536 B
#define SMB_TOT (16 * 16 * 2 * 32 * 4)

__global__ __launch_bounds__(GT, 1) void gemm_mma_kernel(
    const float* __restrict__ Wn,
    const float* __restrict__ Ws,
    const float* __restrict__ bias,
    float* __restrict__ out,
    int n_dst) {
    extern __shared__ uint32_t sB[];
    int tid  = threadIdx.x;
    int wid  = tid >> 5;
    int lane = tid & 31;

    // ---- stage B once: packed half2 fp16 fragments ----
#pragma unroll
    for (int i = 0; i < 64; i++) {
        int slot   = i * GT + tid;
        int l      = slot & 31;
        int half_  = (slot >> 5) & 1;
        int kb     = (slot >> 6) & 15;
        int nblock = slot >> 10;
        int n  = nblock * 8 + (l >> 2);
        int k0 = kb * 16 + half_ * 8 + (l & 3) * 2;
        float flo = (k0     < 128) ? __ldg(Wn + n * 128 + k0)     : __ldg(Ws + n * 128 + k0 - 128);
        float fhi = (k0 + 1 < 128) ? __ldg(Wn + n * 128 + k0 + 1) : __ldg(Ws + n * 128 + k0 - 127);
        __half2 hp = __floats2half2_rn(flo, fhi);
        sB[slot] = *reinterpret_cast<uint32_t*>(&hp);
    }
    __syncthreads();

    int colq = (lane & 3) * 2;
    int rowq = lane >> 2;

    const uint32_t* plane = reinterpret_cast<const uint32_t*>(g_plane);
    int ntiles = (n_dst + 255) >> 8;

    for (int tile = blockIdx.x; tile < ntiles; tile += gridDim.x) {
        int m0  = tile << 8;
        int r0w = m0 + wid * 32;      // this warp's 32 rows

        float acc[2][16][4];
#pragma unroll
        for (int mi = 0; mi < 2; mi++)
#pragma unroll
            for (int j = 0; j < 16; j++)
#pragma unroll
                for (int r = 0; r < 4; r++) acc[mi][j][r] = 0.f;

#pragma unroll 2
        for (int kb = 0; kb < 16; kb++) {
            uint32_t a[2][4];
#pragma unroll
            for (int mi = 0; mi < 2; mi++) {
                int rb = r0w + mi * 16;
                size_t b0 = ((size_t)(2 * kb) * NPAD + rb) * 4;
                size_t b1 = b0 + (size_t)NPAD * 4;
                a[mi][0] = __ldg(plane + b0 + lane);
                a[mi][1] = __ldg(plane + b0 + 32 + lane);
                a[mi][2] = __ldg(plane + b1 + lane);
                a[mi][3] = __ldg(plane + b1 + 32 + lane);
            }
#pragma unroll
            for (int nf = 0; nf < 16; nf++) {
                uint32_t bf[2];
                bf[0] = sB[(((nf * 16 + kb) * 2) + 0) * 32 + lane];
                bf[1] = sB[(((nf * 16 + kb) * 2) + 1) * 32 + lane];
                mma_f16(acc[0][nf], a[0], bf);
                mma_f16(acc[1][nf], a[1], bf);
            }
        }

        // ---- epilogue: bias + store ----
#pragma unroll
        for (int mi = 0; mi < 2; mi++) {
            int r0 = r0w + mi * 16 + rowq;
            int r1 = r0 + 8;
#pragma unroll
            for (int nf = 0; nf < 16; nf++) {
                int col = nf * 8 + colq;
                float2 b2 = *reinterpret_cast<const float2*>(bias + col);
                if (r0 < n_dst) {
                    float2 o = make_float2(acc[mi][nf][0] + b2.x, acc[mi][nf][1] + b2.y);
                    *reinterpret_cast<float2*>(out + (size_t)r0 * F_OUT_C + col) = o;
                }
                if (r1 < n_dst) {
                    float2 o = make_float2(acc[mi][nf][2] + b2.x, acc[mi][nf][3] + b2.y);
                    *reinterpret_cast<float2*>(out + (size_t)r1 * F_OUT_C + col) = o;
                }
            }
        }
    }
}

// ---------------------------------------------------------------------------
// Launch
// ---------------------------------------------------------------------------
extern "C" void kernel_launch(void* const* d_in, const int* in_sizes, int n_in,
                              void* d_out, int out_size) {
    const int*   codes    = (const int*)d_in[0];
    const int*   indices  = (const int*)d_in[1];
    const int*   indptr   = (const int*)d_in[2];
    const float* h_self   = (const float*)d_in[3];
    const float* codebook = (const float*)d_in[4];
    const float* Wn       = (const float*)d_in[5];
    const float* Ws       = (const float*)d_in[6];
    const float* b_self   = (const float*)d_in[7];
    float* out = (float*)d_out;

    int n_dst = in_sizes[2] - 1;

    {
        const int cb_bytes = P_C * 256 * W_C * 2;   // 65536 (fp16)
        cudaFuncSetAttribute(gather_fused_kernel,
                             cudaFuncAttributeMaxDynamicSharedMemorySize, cb_bytes);
        gather_fused_kernel<<<GW_BLOCKS, GW_THREADS, cb_bytes>>>(
            codes, indices, indptr, codebook, h_self, n_dst);
    }
    {
        cudaFuncSetAttribute(gemm_mma_kernel,
                             cudaFuncAttributeMaxDynamicSharedMemorySize, SMB_TOT);
        gemm_mma_kernel<<<GEMM_GRID, GT, SMB_TOT>>>(
            Wn, Ws, b_self, out, n_dst);
    }
}

// round 14
// speedup vs baseline: 1.3638x; 1.0250x over previous
#include <cuda_runtime.h>
#include <cuda_fp16.h>
#include <cstdint>
#include <cstddef>

#define P_C     16
#define W_C     8
#define F_IN_C  128
#define F_OUT_C 128
#define NPAD    100352   // padded dst count

// fp16 plane scratch: plane[kc][dst] = uint4 = 8 halfs, natural k order.
// kc 0..15 : neighbor features k = kc*8..+7 ; kc 16..31 : self features
__device__ uint4 g_plane[(size_t)32 * NPAD];

// ---------------------------------------------------------------------------
// Kernel 1: fused decode+gather+mean + h_self conversion.
// ALL lanes run the warp-collective gather (shfl needs full warp); lanes>=16
// then replace their result with the self-feature conversion (kc = lane).
// Results staged in smem and flushed transposed: warp kc=wid stores 32
// consecutive dsts of its plane as one contiguous 512B STG.
// ---------------------------------------------------------------------------
#define GW_THREADS 1024
#define GW_BLOCKS  296
// smem: 16384 half2 codebook (64 KB) + 32*33 uint4 staging (16896 B)
#define GW_SMEM (65536 + 32 * 33 * 16)

__global__ __launch_bounds__(GW_THREADS, 2) void gather_fused_kernel(
    const int* __restrict__ codes,
    const int* __restrict__ indices,
    const int* __restrict__ indptr,
    const float* __restrict__ codebook,
    const float* __restrict__ hself,
    int n_dst) {
    extern __shared__ __half2 cbh[];                      // [16384] half2 = 64 KB
    uint4* stag = reinterpret_cast<uint4*>(cbh + 16384);  // [32][33] uint4

    int tid  = threadIdx.x;
    int lane = tid & 31;
    int wid  = tid >> 5;

#pragma unroll
    for (int i = 0; i < 4; i++) {
        int blk = i * GW_THREADS + tid;
        const float4* s = reinterpret_cast<const float4*>(codebook + blk * 8);
        float4 a = __ldg(s);
        float4 b = __ldg(s + 1);
        __half2 h0 = __floats2half2_rn(a.x, a.y);
        __half2 h1 = __floats2half2_rn(a.z, a.w);
        __half2 h2 = __floats2half2_rn(b.x, b.y);
        __half2 h3 = __floats2half2_rn(b.z, b.w);
        uint4 pk;
        pk.x = *reinterpret_cast<uint32_t*>(&h0);
        pk.y = *reinterpret_cast<uint32_t*>(&h1);
        pk.z = *reinterpret_cast<uint32_t*>(&h2);
        pk.w = *reinterpret_cast<uint32_t*>(&h3);
        reinterpret_cast<uint4*>(cbh)[blk] = pk;
    }
    __syncthreads();

    int p = lane & 15;
    int h = lane >> 4;
    const __half2* cb_p = cbh + (p << 10);

    int stride = GW_BLOCKS * 32;
    for (int base = blockIdx.x * 32; base < n_dst; base += stride) {
        int dst = base + wid;
        if (dst < n_dst) {
            int start = __ldg(indptr + dst);
            int deg   = __ldg(indptr + dst + 1) - start;

            float4 lo, hi;   // valid on lanes<16 after combine

            if (deg == 16) {
                int my_idx = __ldg(indices + start + (lane & 15));
                int c[8];
#pragma unroll
                for (int s = 0; s < 8; s++) {
                    int src = __shfl_sync(0xffffffffu, my_idx, 2 * s + h);
                    c[s] = __ldg(codes + src * P_C + p);
                }
                __half2 a0 = __float2half2_rn(0.f), a1 = a0, a2 = a0, a3 = a0;
#pragma unroll
                for (int s = 0; s < 8; s++) {
                    uint4 v = *reinterpret_cast<const uint4*>(cb_p + c[s] * 4);
                    a0 = __hadd2(a0, *reinterpret_cast<__half2*>(&v.x));
                    a1 = __hadd2(a1, *reinterpret_cast<__half2*>(&v.y));
                    a2 = __hadd2(a2, *reinterpret_cast<__half2*>(&v.z));
                    a3 = __hadd2(a3, *reinterpret_cast<__half2*>(&v.w));
                }
                uint32_t u0 = *reinterpret_cast<uint32_t*>(&a0);
                uint32_t u1 = *reinterpret_cast<uint32_t*>(&a1);
                uint32_t u2 = *reinterpret_cast<uint32_t*>(&a2);
                uint32_t u3 = *reinterpret_cast<uint32_t*>(&a3);
                uint32_t q0 = __shfl_down_sync(0xffffffffu, u0, 16);
                uint32_t q1 = __shfl_down_sync(0xffffffffu, u1, 16);
                uint32_t q2 = __shfl_down_sync(0xffffffffu, u2, 16);
                uint32_t q3 = __shfl_down_sync(0xffffffffu, u3, 16);
                float2 f0 = __half22float2(*reinterpret_cast<__half2*>(&u0));
                float2 f1 = __half22float2(*reinterpret_cast<__half2*>(&u1));
                float2 f2 = __half22float2(*reinterpret_cast<__half2*>(&u2));
                float2 f3 = __half22float2(*reinterpret_cast<__half2*>(&u3));
                float2 g0 = __half22float2(*reinterpret_cast<__half2*>(&q0));
                float2 g1 = __half22float2(*reinterpret_cast<__half2*>(&q1));
                float2 g2 = __half22float2(*reinterpret_cast<__half2*>(&q2));
                float2 g3 = __half22float2(*reinterpret_cast<__half2*>(&q3));
                const float s16 = 1.0f / 16.0f;
                lo = make_float4((f0.x + g0.x) * s16, (f0.y + g0.y) * s16,
                                 (f1.x + g1.x) * s16, (f1.y + g1.y) * s16);
                hi = make_float4((f2.x + g2.x) * s16, (f2.y + g2.y) * s16,
                                 (f3.x + g3.x) * s16, (f3.y + g3.y) * s16);
            } else {
                float4 acc = make_float4(0.f, 0.f, 0.f, 0.f);
                for (int e = 0; e < deg; e++) {
                    int src = __ldg(indices + start + e);
                    int c = __ldg(codes + src * P_C + p);
                    __half2 a = cb_p[c * 4 + h * 2];
                    __half2 b = cb_p[c * 4 + h * 2 + 1];
                    float2 fa = __half22float2(a), fb = __half22float2(b);
                    acc.x += fa.x; acc.y += fa.y; acc.z += fb.x; acc.w += fb.y;
                }
                float s = 1.0f / fmaxf((float)deg, 1.0f);
                acc.x *= s; acc.y *= s; acc.z *= s; acc.w *= s;
                float4 acch;
                acch.x = __shfl_down_sync(0xffffffffu, acc.x, 16);
                acch.y = __shfl_down_sync(0xffffffffu, acc.y, 16);
                acch.z = __shfl_down_sync(0xffffffffu, acc.z, 16);
                acch.w = __shfl_down_sync(0xffffffffu, acc.w, 16);
                lo = acc; hi = acch;
            }

            uint4 pk;
            if (lane < 16) {
                __half2 q0 = __floats2half2_rn(lo.x, lo.y);
                __half2 q1 = __floats2half2_rn(lo.z, lo.w);
                __half2 q2 = __floats2half2_rn(hi.x, hi.y);
                __half2 q3 = __floats2half2_rn(hi.z, hi.w);
                pk.x = *reinterpret_cast<uint32_t*>(&q0);
                pk.y = *reinterpret_cast<uint32_t*>(&q1);
                pk.z = *reinterpret_cast<uint32_t*>(&q2);
                pk.w = *reinterpret_cast<uint32_t*>(&q3);
            } else {
                // self features: kc = 16 + p (== lane)
                const float4* hs = reinterpret_cast<const float4*>(
                    hself + (size_t)dst * F_IN_C + p * 8);
                float4 a = __ldg(hs);
                float4 b = __ldg(hs + 1);
                __half2 q0 = __floats2half2_rn(a.x, a.y);
                __half2 q1 = __floats2half2_rn(a.z, a.w);
                __half2 q2 = __floats2half2_rn(b.x, b.y);
                __half2 q3 = __floats2half2_rn(b.z, b.w);
                pk.x = *reinterpret_cast<uint32_t*>(&q0);
                pk.y = *reinterpret_cast<uint32_t*>(&q1);
                pk.z = *reinterpret_cast<uint32_t*>(&q2);
                pk.w = *reinterpret_cast<uint32_t*>(&q3);
            }
            stag[wid * 33 + lane] = pk;   // kc == lane
        }
        __syncthreads();
        // flush: warp kc=wid writes 32 consecutive dsts of its plane
        if (base + lane < n_dst)
            g_plane[(size_t)wid * NPAD + base + lane] = stag[lane * 33 + wid];
        __syncthreads();
    }
}

// ---------------------------------------------------------------------------
// Kernel 2: fp16 mma.sync (m16n8k16) GEMM. Warp tile 32(M) x 128(N),
// CTA tile 256(M) x 128(N), 8 warps along M. A fragments register-pipelined
// one kb ahead (L2 latency hidden under MMA+LDS of current kb).
// ---------------------------------------------------------------------------
__device__ __forceinline__ void mma_f16(float* d, const uint32_t* a, const uint32_t* b) {
    asm volatile(
        "mma.sync.aligned.m16n8k16.row.col.f32.f16.f16.f32 "
        "{%0,%1,%2,%3}, {%4,%5,%6,%7}, {%8,%9}, {%0,%1,%2,%3};"
        : "+f"(d[0]), "+f"(d[1]), "+f"(d[2]), "+f"(d[3])
        : "r"(a[0]), "r"(a[1]), "r"(a[2]), "r"(a[3]), "r"(b[0]), "r"(b[1]));
}

#define GT        256
#define GEMM_GRID 148
#define SMB_TOT (16 * 16 * 2 * 32 * 4)

__device__ __forceinline__ void load_a_kb(uint32_t a[2][4],
                                          const uint32_t* __restrict__ plane,
                                          int kb, int r0w, int lane) {
#pragma unroll
    for (int mi = 0; mi < 2; mi++) {
        int rb = r0w + mi * 16;
        size_t b0 = ((size_t)(2 * kb) * NPAD + rb) * 4;
        size_t b1 = b0 + (size_t)NPAD * 4;
        a[mi][0] = __ldg(plane + b0 + lane);
        a[mi][1] = __ldg(plane + b0 + 32 + lane);
        a[mi][2] = __ldg(plane + b1 + lane);
        a[mi][3] = __ldg(plane + b1 + 32 + lane);
    }
}

__global__ __launch_bounds__(GT, 1) void gemm_mma_kernel(
    const float* __restrict__ Wn,
    const float* __restrict__ Ws,
    const float* __restrict__ bias,
    float* __restrict__ out,
    int n_dst) {
    extern __shared__ uint32_t sB[];
    int tid  = threadIdx.x;
    int wid  = tid >> 5;
    int lane = tid & 31;

    // ---- stage B once: packed half2 fp16 fragments ----
#pragma unroll
    for (int i = 0; i < 64; i++) {
        int slot   = i * GT + tid;
        int l      = slot & 31;
        int half_  = (slot >> 5) & 1;
        int kb     = (slot >> 6) & 15;
        int nblock = slot >> 10;
        int n  = nblock * 8 + (l >> 2);
        int k0 = kb * 16 + half_ * 8 + (l & 3) * 2;
        float flo = (k0     < 128) ? __ldg(Wn + n * 128 + k0)     : __ldg(Ws + n * 128 + k0 - 128);
        float fhi = (k0 + 1 < 128) ? __ldg(Wn + n * 128 + k0 + 1) : __ldg(Ws + n * 128 + k0 - 127);
        __half2 hp = __floats2half2_rn(flo, fhi);
        sB[slot] = *reinterpret_cast<uint32_t*>(&hp);
    }
    __syncthreads();

    int colq = (lane & 3) * 2;
    int rowq = lane >> 2;

    const uint32_t* plane = reinterpret_cast<const uint32_t*>(g_plane);
    int ntiles = (n_dst + 255) >> 8;

    for (int tile = blockIdx.x; tile < ntiles; tile += gridDim.x) {
        int m0  = tile << 8;
        int r0w = m0 + wid * 32;

        float acc[2][16][4];
#pragma unroll
        for (int mi = 0; mi < 2; mi++)
#pragma unroll
            for (int j = 0; j < 16; j++)
#pragma unroll
                for (int r = 0; r < 4; r++) acc[mi][j][r] = 0.f;

        uint32_t a[2][4];
        load_a_kb(a, plane, 0, r0w, lane);

#pragma unroll
        for (int kb = 0; kb < 16; kb++) {
            uint32_t an[2][4];
            if (kb < 15) load_a_kb(an, plane, kb + 1, r0w, lane);
#pragma unroll
            for (int nf = 0; nf < 16; nf++) {
                uint32_t bf[2];
                bf[0] = sB[(((nf * 16 + kb) * 2) + 0) * 32 + lane];
                bf[1] = sB[(((nf * 16 + kb) * 2) + 1) * 32 + lane];
                mma_f16(acc[0][nf], a[0], bf);
                mma_f16(acc[1][nf], a[1], bf);
            }
            if (kb < 15) {
#pragma unroll
                for (int mi = 0; mi < 2; mi++)
#pragma unroll
                    for (int r = 0; r < 4; r++) a[mi][r] = an[mi][r];
            }
        }

        // ---- epilogue: bias + store ----
#pragma unroll
        for (int mi = 0; mi < 2; mi++) {
            int r0 = r0w + mi * 16 + rowq;
            int r1 = r0 + 8;
#pragma unroll
            for (int nf = 0; nf < 16; nf++) {
                int col = nf * 8 + colq;
                float2 b2 = *reinterpret_cast<const float2*>(bias + col);
                if (r0 < n_dst) {
                    float2 o = make_float2(acc[mi][nf][0] + b2.x, acc[mi][nf][1] + b2.y);
                    *reinterpret_cast<float2*>(out + (size_t)r0 * F_OUT_C + col) = o;
                }
                if (r1 < n_dst) {
                    float2 o = make_float2(acc[mi][nf][2] + b2.x, acc[mi][nf][3] + b2.y);
                    *reinterpret_cast<float2*>(out + (size_t)r1 * F_OUT_C + col) = o;
                }
            }
        }
    }
}

// ---------------------------------------------------------------------------
// Launch
// ---------------------------------------------------------------------------
extern "C" void kernel_launch(void* const* d_in, const int* in_sizes, int n_in,
                              void* d_out, int out_size) {
    const int*   codes    = (const int*)d_in[0];
    const int*   indices  = (const int*)d_in[1];
    const int*   indptr   = (const int*)d_in[2];
    const float* h_self   = (const float*)d_in[3];
    const float* codebook = (const float*)d_in[4];
    const float* Wn       = (const float*)d_in[5];
    const float* Ws       = (const float*)d_in[6];
    const float* b_self   = (const float*)d_in[7];
    float* out = (float*)d_out;

    int n_dst = in_sizes[2] - 1;

    {
        cudaFuncSetAttribute(gather_fused_kernel,
                             cudaFuncAttributeMaxDynamicSharedMemorySize, GW_SMEM);
        gather_fused_kernel<<<GW_BLOCKS, GW_THREADS, GW_SMEM>>>(
            codes, indices, indptr, codebook, h_self, n_dst);
    }
    {
        cudaFuncSetAttribute(gemm_mma_kernel,
                             cudaFuncAttributeMaxDynamicSharedMemorySize, SMB_TOT);
        gemm_mma_kernel<<<GEMM_GRID, GT, SMB_TOT>>>(
            Wn, Ws, b_self, out, n_dst);
    }
}

// round 15
// speedup vs baseline: 1.4446x; 1.0592x over previous
#include <cuda_runtime.h>
#include <cuda_fp16.h>
#include <cstdint>
#include <cstddef>

#define P_C     16
#define W_C     8
#define F_IN_C  128
#define F_OUT_C 128
#define NPAD    100352   // padded dst count

// fp16 plane scratch: plane[kc][dst] = uint4 = 8 halfs, natural k order.
// kc 0..15 : neighbor features k = kc*8..+7 ; kc 16..31 : self features
__device__ uint4 g_plane[(size_t)32 * NPAD];

// ---------------------------------------------------------------------------
// Kernel 1: fused decode+gather+mean + h_self conversion.
// 2 dsts per warp per barrier epoch (independent streams for MLP).
// Staged in smem, flushed transposed (warp kc writes 64 consecutive dsts).
// ---------------------------------------------------------------------------
#define GW_THREADS 1024
#define GW_BLOCKS  296
// smem: 16384 half2 codebook (64 KB) + 64*33 uint4 staging (33792 B)
#define GW_SMEM (65536 + 64 * 33 * 16)

__global__ __launch_bounds__(GW_THREADS, 2) void gather_fused_kernel(
    const int* __restrict__ codes,
    const int* __restrict__ indices,
    const int* __restrict__ indptr,
    const float* __restrict__ codebook,
    const float* __restrict__ hself,
    int n_dst) {
    extern __shared__ __half2 cbh[];                      // [16384] half2 = 64 KB
    uint4* stag = reinterpret_cast<uint4*>(cbh + 16384);  // [64][33] uint4

    int tid  = threadIdx.x;
    int lane = tid & 31;
    int wid  = tid >> 5;

#pragma unroll
    for (int i = 0; i < 4; i++) {
        int blk = i * GW_THREADS + tid;
        const float4* s = reinterpret_cast<const float4*>(codebook + blk * 8);
        float4 a = __ldg(s);
        float4 b = __ldg(s + 1);
        __half2 h0 = __floats2half2_rn(a.x, a.y);
        __half2 h1 = __floats2half2_rn(a.z, a.w);
        __half2 h2 = __floats2half2_rn(b.x, b.y);
        __half2 h3 = __floats2half2_rn(b.z, b.w);
        uint4 pk;
        pk.x = *reinterpret_cast<uint32_t*>(&h0);
        pk.y = *reinterpret_cast<uint32_t*>(&h1);
        pk.z = *reinterpret_cast<uint32_t*>(&h2);
        pk.w = *reinterpret_cast<uint32_t*>(&h3);
        reinterpret_cast<uint4*>(cbh)[blk] = pk;
    }
    __syncthreads();

    int p = lane & 15;
    int h = lane >> 4;
    const __half2* cb_p = cbh + (p << 10);

    int stride = GW_BLOCKS * 64;
    for (int base = blockIdx.x * 64; base < n_dst; base += stride) {
#pragma unroll
        for (int u = 0; u < 2; u++) {
            int dst = base + u * 32 + wid;
            if (dst < n_dst) {
                int start = __ldg(indptr + dst);
                int deg   = __ldg(indptr + dst + 1) - start;

                float4 lo, hi;   // valid on lanes<16 after combine

                if (deg == 16) {
                    int my_idx = __ldg(indices + start + (lane & 15));
                    int c[8];
#pragma unroll
                    for (int s = 0; s < 8; s++) {
                        int src = __shfl_sync(0xffffffffu, my_idx, 2 * s + h);
                        c[s] = __ldg(codes + src * P_C + p);
                    }
                    __half2 a0 = __float2half2_rn(0.f), a1 = a0, a2 = a0, a3 = a0;
#pragma unroll
                    for (int s = 0; s < 8; s++) {
                        uint4 v = *reinterpret_cast<const uint4*>(cb_p + c[s] * 4);
                        a0 = __hadd2(a0, *reinterpret_cast<__half2*>(&v.x));
                        a1 = __hadd2(a1, *reinterpret_cast<__half2*>(&v.y));
                        a2 = __hadd2(a2, *reinterpret_cast<__half2*>(&v.z));
                        a3 = __hadd2(a3, *reinterpret_cast<__half2*>(&v.w));
                    }
                    uint32_t u0 = *reinterpret_cast<uint32_t*>(&a0);
                    uint32_t u1 = *reinterpret_cast<uint32_t*>(&a1);
                    uint32_t u2 = *reinterpret_cast<uint32_t*>(&a2);
                    uint32_t u3 = *reinterpret_cast<uint32_t*>(&a3);
                    uint32_t q0 = __shfl_down_sync(0xffffffffu, u0, 16);
                    uint32_t q1 = __shfl_down_sync(0xffffffffu, u1, 16);
                    uint32_t q2 = __shfl_down_sync(0xffffffffu, u2, 16);
                    uint32_t q3 = __shfl_down_sync(0xffffffffu, u3, 16);
                    float2 f0 = __half22float2(*reinterpret_cast<__half2*>(&u0));
                    float2 f1 = __half22float2(*reinterpret_cast<__half2*>(&u1));
                    float2 f2 = __half22float2(*reinterpret_cast<__half2*>(&u2));
                    float2 f3 = __half22float2(*reinterpret_cast<__half2*>(&u3));
                    float2 g0 = __half22float2(*reinterpret_cast<__half2*>(&q0));
                    float2 g1 = __half22float2(*reinterpret_cast<__half2*>(&q1));
                    float2 g2 = __half22float2(*reinterpret_cast<__half2*>(&q2));
                    float2 g3 = __half22float2(*reinterpret_cast<__half2*>(&q3));
                    const float s16 = 1.0f / 16.0f;
                    lo = make_float4((f0.x + g0.x) * s16, (f0.y + g0.y) * s16,
                                     (f1.x + g1.x) * s16, (f1.y + g1.y) * s16);
                    hi = make_float4((f2.x + g2.x) * s16, (f2.y + g2.y) * s16,
                                     (f3.x + g3.x) * s16, (f3.y + g3.y) * s16);
                } else {
                    float4 acc = make_float4(0.f, 0.f, 0.f, 0.f);
                    for (int e = 0; e < deg; e++) {
                        int src = __ldg(indices + start + e);
                        int c = __ldg(codes + src * P_C + p);
                        __half2 a = cb_p[c * 4 + h * 2];
                        __half2 b = cb_p[c * 4 + h * 2 + 1];
                        float2 fa = __half22float2(a), fb = __half22float2(b);
                        acc.x += fa.x; acc.y += fa.y; acc.z += fb.x; acc.w += fb.y;
                    }
                    float s = 1.0f / fmaxf((float)deg, 1.0f);
                    acc.x *= s; acc.y *= s; acc.z *= s; acc.w *= s;
                    float4 acch;
                    acch.x = __shfl_down_sync(0xffffffffu, acc.x, 16);
                    acch.y = __shfl_down_sync(0xffffffffu, acc.y, 16);
                    acch.z = __shfl_down_sync(0xffffffffu, acc.z, 16);
                    acch.w = __shfl_down_sync(0xffffffffu, acc.w, 16);
                    lo = acc; hi = acch;
                }

                uint4 pk;
                if (lane < 16) {
                    __half2 q0 = __floats2half2_rn(lo.x, lo.y);
                    __half2 q1 = __floats2half2_rn(lo.z, lo.w);
                    __half2 q2 = __floats2half2_rn(hi.x, hi.y);
                    __half2 q3 = __floats2half2_rn(hi.z, hi.w);
                    pk.x = *reinterpret_cast<uint32_t*>(&q0);
                    pk.y = *reinterpret_cast<uint32_t*>(&q1);
                    pk.z = *reinterpret_cast<uint32_t*>(&q2);
                    pk.w = *reinterpret_cast<uint32_t*>(&q3);
                } else {
                    // self features: kc = 16 + p (== lane)
                    const float4* hs = reinterpret_cast<const float4*>(
                        hself + (size_t)dst * F_IN_C + p * 8);
                    float4 a = __ldg(hs);
                    float4 b = __ldg(hs + 1);
                    __half2 q0 = __floats2half2_rn(a.x, a.y);
                    __half2 q1 = __floats2half2_rn(a.z, a.w);
                    __half2 q2 = __floats2half2_rn(b.x, b.y);
                    __half2 q3 = __floats2half2_rn(b.z, b.w);
                    pk.x = *reinterpret_cast<uint32_t*>(&q0);
                    pk.y = *reinterpret_cast<uint32_t*>(&q1);
                    pk.z = *reinterpret_cast<uint32_t*>(&q2);
                    pk.w = *reinterpret_cast<uint32_t*>(&q3);
                }
                stag[(u * 32 + wid) * 33 + lane] = pk;   // kc == lane
            }
        }
        __syncthreads();
        // flush: warp kc=wid writes 64 consecutive dsts of its plane
#pragma unroll
        for (int u = 0; u < 2; u++) {
            int d = base + u * 32 + lane;
            if (d < n_dst)
                g_plane[(size_t)wid * NPAD + d] = stag[(u * 32 + lane) * 33 + wid];
        }
        __syncthreads();
    }
}

// ---------------------------------------------------------------------------
// Kernel 2: fp16 mma.sync (m16n8k16) GEMM. 512 thr, 16 warps: 8 M-groups x
// 2 N-groups; warp tile 32(M) x 64(N); CTA tile 256(M) x 128(N).
// A register-pipelined one kb ahead. 16 warps/SM doubles issue slots vs R14.
// ---------------------------------------------------------------------------
__device__ __forceinline__ void mma_f16(float* d, const uint32_t* a, const uint32_t* b) {
    asm volatile(
        "mma.sync.aligned.m16n8k16.row.col.f32.f16.f16.f32 "
        "{%0,%1,%2,%3}, {%4,%5,%6,%7}, {%8,%9}, {%0,%1,%2,%3};"
        : "+f"(d[0]), "+f"(d[1]), "+f"(d[2]), "+f"(d[3])
        : "r"(a[0]), "r"(a[1]), "r"(a[2]), "r"(a[3]), "r"(b[0]), "r"(b[1]));
}

#define GT        512
#define GEMM_GRID 148
#define SMB_TOT (16 * 16 * 2 * 32 * 4)

__device__ __forceinline__ void load_a_kb(uint32_t a[2][4],
                                          const uint32_t* __restrict__ plane,
                                          int kb, int r0w, int lane) {
#pragma unroll
    for (int mi = 0; mi < 2; mi++) {
        int rb = r0w + mi * 16;
        size_t b0 = ((size_t)(2 * kb) * NPAD + rb) * 4;
        size_t b1 = b0 + (size_t)NPAD * 4;
        a[mi][0] = __ldg(plane + b0 + lane);
        a[mi][1] = __ldg(plane + b0 + 32 + lane);
        a[mi][2] = __ldg(plane + b1 + lane);
        a[mi][3] = __ldg(plane + b1 + 32 + lane);
    }
}

__global__ __launch_bounds__(GT, 1) void gemm_mma_kernel(
    const float* __restrict__ Wn,
    const float* __restrict__ Ws,
    const float* __restrict__ bias,
    float* __restrict__ out,
    int n_dst) {
    extern __shared__ uint32_t sB[];
    int tid  = threadIdx.x;
    int wid  = tid >> 5;
    int lane = tid & 31;
    int wm   = wid >> 1;   // 0..7 : rows wm*32..+31
    int wn   = wid & 1;    // 0..1 : cols wn*64..+63

    // ---- stage B once: packed half2 fp16 fragments ----
#pragma unroll
    for (int i = 0; i < 32; i++) {
        int slot   = i * GT + tid;
        int l      = slot & 31;
        int half_  = (slot >> 5) & 1;
        int kb     = (slot >> 6) & 15;
        int nblock = slot >> 10;
        int n  = nblock * 8 + (l >> 2);
        int k0 = kb * 16 + half_ * 8 + (l & 3) * 2;
        float flo = (k0     < 128) ? __ldg(Wn + n * 128 + k0)     : __ldg(Ws + n * 128 + k0 - 128);
        float fhi = (k0 + 1 < 128) ? __ldg(Wn + n * 128 + k0 + 1) : __ldg(Ws + n * 128 + k0 - 127);
        __half2 hp = __floats2half2_rn(flo, fhi);
        sB[slot] = *reinterpret_cast<uint32_t*>(&hp);
    }
    __syncthreads();

    int colq = (lane & 3) * 2;
    int rowq = lane >> 2;

    const uint32_t* plane = reinterpret_cast<const uint32_t*>(g_plane);
    int ntiles = (n_dst + 255) >> 8;

    for (int tile = blockIdx.x; tile < ntiles; tile += gridDim.x) {
        int m0  = tile << 8;
        int r0w = m0 + wm * 32;

        float acc[2][8][4];
#pragma unroll
        for (int mi = 0; mi < 2; mi++)
#pragma unroll
            for (int j = 0; j < 8; j++)
#pragma unroll
                for (int r = 0; r < 4; r++) acc[mi][j][r] = 0.f;

        uint32_t a[2][4];
        load_a_kb(a, plane, 0, r0w, lane);

#pragma unroll
        for (int kb = 0; kb < 16; kb++) {
            uint32_t an[2][4];
            if (kb < 15) load_a_kb(an, plane, kb + 1, r0w, lane);
#pragma unroll
            for (int nf = 0; nf < 8; nf++) {
                int nblock = wn * 8 + nf;
                uint32_t bf[2];
                bf[0] = sB[(((nblock * 16 + kb) * 2) + 0) * 32 + lane];
                bf[1] = sB[(((nblock * 16 + kb) * 2) + 1) * 32 + lane];
                mma_f16(acc[0][nf], a[0], bf);
                mma_f16(acc[1][nf], a[1], bf);
            }
            if (kb < 15) {
#pragma unroll
                for (int mi = 0; mi < 2; mi++)
#pragma unroll
                    for (int r = 0; r < 4; r++) a[mi][r] = an[mi][r];
            }
        }

        // ---- epilogue: bias + store ----
#pragma unroll
        for (int mi = 0; mi < 2; mi++) {
            int r0 = r0w + mi * 16 + rowq;
            int r1 = r0 + 8;
#pragma unroll
            for (int nf = 0; nf < 8; nf++) {
                int col = wn * 64 + nf * 8 + colq;
                float2 b2 = *reinterpret_cast<const float2*>(bias + col);
                if (r0 < n_dst) {
                    float2 o = make_float2(acc[mi][nf][0] + b2.x, acc[mi][nf][1] + b2.y);
                    *reinterpret_cast<float2*>(out + (size_t)r0 * F_OUT_C + col) = o;
                }
                if (r1 < n_dst) {
                    float2 o = make_float2(acc[mi][nf][2] + b2.x, acc[mi][nf][3] + b2.y);
                    *reinterpret_cast<float2*>(out + (size_t)r1 * F_OUT_C + col) = o;
                }
            }
        }
    }
}

// ---------------------------------------------------------------------------
// Launch
// ---------------------------------------------------------------------------
extern "C" void kernel_launch(void* const* d_in, const int* in_sizes, int n_in,
                              void* d_out, int out_size) {
    const int*   codes    = (const int*)d_in[0];
    const int*   indices  = (const int*)d_in[1];
    const int*   indptr   = (const int*)d_in[2];
    const float* h_self   = (const float*)d_in[3];
    const float* codebook = (const float*)d_in[4];
    const float* Wn       = (const float*)d_in[5];
    const float* Ws       = (const float*)d_in[6];
    const float* b_self   = (const float*)d_in[7];
    float* out = (float*)d_out;

    int n_dst = in_sizes[2] - 1;

    {
        cudaFuncSetAttribute(gather_fused_kernel,
                             cudaFuncAttributeMaxDynamicSharedMemorySize, GW_SMEM);
        gather_fused_kernel<<<GW_BLOCKS, GW_THREADS, GW_SMEM>>>(
            codes, indices, indptr, codebook, h_self, n_dst);
    }
    {
        cudaFuncSetAttribute(gemm_mma_kernel,
                             cudaFuncAttributeMaxDynamicSharedMemorySize, SMB_TOT);
        gemm_mma_kernel<<<GEMM_GRID, GT, SMB_TOT>>>(
            Wn, Ws, b_self, out, n_dst);
    }
}